// round 4
// baseline (speedup 1.0000x reference)
#include <cuda_runtime.h>
#include <cuda_bf16.h>
#include <mma.h>
#include <cstdint>
#include <math.h>

using namespace nvcuda;

// Problem constants
#define B_   2
#define T_   2048
#define C_   512
#define H_   8
#define D_   64
#define BH_  (B_*H_)
#define L_   128
#define NC_  (T_/L_)
#define M_   (B_*T_)
#define EPS_ 1e-8f

// Scratch (device globals)
__device__ float g_phiq[BH_*T_*D_];
__device__ float g_phik[BH_*T_*D_];
__device__ float g_v   [BH_*T_*D_];
__device__ float g_kv  [BH_*NC_*D_*D_];
__device__ float g_ks  [BH_*NC_*D_];

// bf16 hi/lo split buffers
__device__ __nv_bfloat16 g_xhi[M_*C_],  g_xlo[M_*C_];
__device__ __nv_bfloat16 g_wqh[C_*3*C_], g_wql[C_*3*C_];
__device__ __nv_bfloat16 g_wph[C_*C_],  g_wpl[C_*C_];
__device__ __nv_bfloat16 g_yhi[M_*C_],  g_ylo[M_*C_];

__device__ __forceinline__ float phi_fn(float x) {
    return (x > 0.f) ? (x + 1.f) : __expf(x);
}

// ---------------------------------------------------------------------------
// Split fp32 -> bf16 hi/lo
// ---------------------------------------------------------------------------
__global__ void __launch_bounds__(256)
split_kernel(const float* __restrict__ src,
             __nv_bfloat16* __restrict__ hi,
             __nv_bfloat16* __restrict__ lo, int n4)
{
    int i = blockIdx.x * blockDim.x + threadIdx.x;
    if (i >= n4) return;
    float4 v = ((const float4*)src)[i];
    float vv[4] = {v.x, v.y, v.z, v.w};
    __nv_bfloat162 h2[2], l2[2];
#pragma unroll
    for (int p = 0; p < 2; p++) {
        __nv_bfloat16 h0 = __float2bfloat16(vv[p*2]);
        __nv_bfloat16 h1 = __float2bfloat16(vv[p*2+1]);
        h2[p].x = h0; h2[p].y = h1;
        l2[p].x = __float2bfloat16(vv[p*2]   - __bfloat162float(h0));
        l2[p].y = __float2bfloat16(vv[p*2+1] - __bfloat162float(h1));
    }
    ((__nv_bfloat162*)hi)[i*2]   = h2[0];
    ((__nv_bfloat162*)hi)[i*2+1] = h2[1];
    ((__nv_bfloat162*)lo)[i*2]   = l2[0];
    ((__nv_bfloat162*)lo)[i*2+1] = l2[1];
}

// ---------------------------------------------------------------------------
// Double-buffered wmma bf16 GEMM (3-term split), pre-split bf16 inputs.
// C[128,64] tile; BK=32; 256 threads = 8 warps (4x2), warp tile 32x32.
// MODE 0: QKV (NW=1536) epilogue bias+phi+mask+scatter (also writes fp32 q/k/v)
// MODE 1: proj (NW=512) epilogue bias+store
// SMEM: per stage: AHI 128x48 bf16 (12288B), ALO, BHI 32x72 (4608B), BLO
//   stage = 33792B, 2 stages = 67584; Cs 128x68 f32 = 34816. total 102400.
// ---------------------------------------------------------------------------
#define G_LDA 48
#define G_LDB 72
#define G_LDC 68
#define G_AHI 0
#define G_ALO 12288
#define G_BHI 24576
#define G_BLO 29184
#define G_STAGE 33792
#define G_CS    (2*G_STAGE)
#define G_SMEM  (G_CS + 34816)

template<int MODE>
__global__ void __launch_bounds__(256)
wmma_gemm_kernel(const __nv_bfloat16* __restrict__ Ahi_g,
                 const __nv_bfloat16* __restrict__ Alo_g,
                 const __nv_bfloat16* __restrict__ Bhi_g,
                 const __nv_bfloat16* __restrict__ Blo_g,
                 const float* __restrict__ bias,
                 const float* __restrict__ am,
                 float* __restrict__ outp)
{
    constexpr int NW = (MODE == 0) ? 1536 : 512;
    extern __shared__ char smem[];
    float* Cs = (float*)(smem + G_CS);

    const int tid = threadIdx.x;
    const int wid = tid >> 5;
    const int bm = blockIdx.x * 128, bn = blockIdx.y * 64;
    const int wr = wid >> 1, wc = wid & 1;

    // A-load mapping: 512 uint4 (8 bf16 each); 2 per thread
    const int ar0 = tid >> 2,            ac0 = (tid & 3) * 8;
    const int ar1 = (256 + tid) >> 2,    ac1 = ((256 + tid) & 3) * 8;
    // B-load mapping: 256 uint4; 1 per thread
    const int br = tid >> 3, bc = (tid & 7) * 8;

    uint4 ra_hi[2], ra_lo[2], rb_hi, rb_lo;

    auto load_regs = [&](int k0) {
        ra_hi[0] = *(const uint4*)&Ahi_g[(size_t)(bm + ar0) * 512 + k0 + ac0];
        ra_hi[1] = *(const uint4*)&Ahi_g[(size_t)(bm + ar1) * 512 + k0 + ac1];
        ra_lo[0] = *(const uint4*)&Alo_g[(size_t)(bm + ar0) * 512 + k0 + ac0];
        ra_lo[1] = *(const uint4*)&Alo_g[(size_t)(bm + ar1) * 512 + k0 + ac1];
        rb_hi    = *(const uint4*)&Bhi_g[(size_t)(k0 + br) * NW + bn + bc];
        rb_lo    = *(const uint4*)&Blo_g[(size_t)(k0 + br) * NW + bn + bc];
    };
    auto store_stage = [&](int s) {
        char* st = smem + s * G_STAGE;
        *(uint4*)(st + G_AHI + (ar0 * G_LDA + ac0) * 2) = ra_hi[0];
        *(uint4*)(st + G_AHI + (ar1 * G_LDA + ac1) * 2) = ra_hi[1];
        *(uint4*)(st + G_ALO + (ar0 * G_LDA + ac0) * 2) = ra_lo[0];
        *(uint4*)(st + G_ALO + (ar1 * G_LDA + ac1) * 2) = ra_lo[1];
        *(uint4*)(st + G_BHI + (br * G_LDB + bc) * 2) = rb_hi;
        *(uint4*)(st + G_BLO + (br * G_LDB + bc) * 2) = rb_lo;
    };

    wmma::fragment<wmma::accumulator, 16, 16, 16, float> acc[2][2];
#pragma unroll
    for (int i = 0; i < 2; i++)
#pragma unroll
        for (int j = 0; j < 2; j++) wmma::fill_fragment(acc[i][j], 0.f);

    load_regs(0);
    store_stage(0);
    __syncthreads();

    for (int kt = 0; kt < 16; kt++) {
        const int cur = kt & 1;
        if (kt < 15) load_regs((kt + 1) * 32);

        const char* st = smem + cur * G_STAGE;
        const __nv_bfloat16* As_hi = (const __nv_bfloat16*)(st + G_AHI);
        const __nv_bfloat16* As_lo = (const __nv_bfloat16*)(st + G_ALO);
        const __nv_bfloat16* Bs_hi = (const __nv_bfloat16*)(st + G_BHI);
        const __nv_bfloat16* Bs_lo = (const __nv_bfloat16*)(st + G_BLO);

#pragma unroll
        for (int kk = 0; kk < 32; kk += 16) {
            wmma::fragment<wmma::matrix_a, 16, 16, 16, __nv_bfloat16, wmma::row_major> ah[2], al[2];
            wmma::fragment<wmma::matrix_b, 16, 16, 16, __nv_bfloat16, wmma::row_major> bh[2], bl[2];
#pragma unroll
            for (int i = 0; i < 2; i++) {
                wmma::load_matrix_sync(ah[i], &As_hi[(wr * 32 + i * 16) * G_LDA + kk], G_LDA);
                wmma::load_matrix_sync(al[i], &As_lo[(wr * 32 + i * 16) * G_LDA + kk], G_LDA);
            }
#pragma unroll
            for (int j = 0; j < 2; j++) {
                wmma::load_matrix_sync(bh[j], &Bs_hi[kk * G_LDB + wc * 32 + j * 16], G_LDB);
                wmma::load_matrix_sync(bl[j], &Bs_lo[kk * G_LDB + wc * 32 + j * 16], G_LDB);
            }
#pragma unroll
            for (int i = 0; i < 2; i++)
#pragma unroll
                for (int j = 0; j < 2; j++) {
                    wmma::mma_sync(acc[i][j], ah[i], bh[j], acc[i][j]);
                    wmma::mma_sync(acc[i][j], ah[i], bl[j], acc[i][j]);
                    wmma::mma_sync(acc[i][j], al[i], bh[j], acc[i][j]);
                }
        }
        if (kt < 15) store_stage(cur ^ 1);
        __syncthreads();
    }

#pragma unroll
    for (int i = 0; i < 2; i++)
#pragma unroll
        for (int j = 0; j < 2; j++)
            wmma::store_matrix_sync(&Cs[(wr * 32 + i * 16) * G_LDC + wc * 32 + j * 16],
                                    acc[i][j], G_LDC, wmma::mem_row_major);
    __syncthreads();

    {
        const int row = tid >> 1;
        const int c0  = (tid & 1) * 32;
        const int m = bm + row;
        const int n0 = bn + c0;

        if (MODE == 0) {
            const int b = m >> 11, t = m & 2047;
            const float maskd = am[((size_t)b * 2048 + t) * 2048 + t];
            const int sec = bn >> 9;
            const int h = (bn & 511) >> 6;
            float* dst = (sec == 0) ? g_phiq : (sec == 1) ? g_phik : g_v;
            const size_t ob = ((size_t)(b * 8 + h) * 2048 + t) * 64 + (n0 & 63);
#pragma unroll
            for (int c4 = 0; c4 < 32; c4 += 4) {
                float4 bi = *(const float4*)&bias[n0 + c4];
                float bb[4] = {bi.x, bi.y, bi.z, bi.w};
                float ov[4];
#pragma unroll
                for (int u = 0; u < 4; u++) {
                    float val = Cs[row * G_LDC + c0 + c4 + u] + bb[u];
                    if (sec == 0)      ov[u] = phi_fn(val);
                    else if (sec == 1) ov[u] = phi_fn(val) * maskd;
                    else               ov[u] = val * maskd;
                }
                float4 o; o.x = ov[0]; o.y = ov[1]; o.z = ov[2]; o.w = ov[3];
                *(float4*)&dst[ob + c4] = o;
            }
        } else {
#pragma unroll
            for (int c4 = 0; c4 < 32; c4 += 4) {
                float4 bi = *(const float4*)&bias[n0 + c4];
                float4 o;
                o.x = Cs[row * G_LDC + c0 + c4 + 0] + bi.x;
                o.y = Cs[row * G_LDC + c0 + c4 + 1] + bi.y;
                o.z = Cs[row * G_LDC + c0 + c4 + 2] + bi.z;
                o.w = Cs[row * G_LDC + c0 + c4 + 3] + bi.w;
                *(float4*)&outp[(size_t)m * 512 + n0 + c4] = o;
            }
        }
    }
}

// ---------------------------------------------------------------------------
// Kernel 2: per-chunk KV outer-product sums (64x64) + K sums (64)
// ---------------------------------------------------------------------------
__global__ void __launch_bounds__(256, 4)
chunk_kv_kernel()
{
    __shared__ float sk2[32 * 64];
    __shared__ float sv2[32 * 64];

    const int tid = threadIdx.x;
    const int bh = blockIdx.x >> 4;
    const int c  = blockIdx.x & 15;

    const int i  = tid >> 2;
    const int jb = (tid & 3) * 16;

    float acc[16];
#pragma unroll
    for (int jj = 0; jj < 16; jj++) acc[jj] = 0.f;
    float ks = 0.f;

    const size_t base = ((size_t)bh * T_ + c * L_) * 64;

    for (int tt0 = 0; tt0 < 128; tt0 += 32) {
#pragma unroll
        for (int q = 0; q < 2; q++) {
            int f = q * 256 + tid;
            int row = f >> 4, d4 = f & 15;
            *(float4*)&sk2[row * 64 + d4 * 4] =
                *(const float4*)&g_phik[base + (size_t)(tt0 + row) * 64 + d4 * 4];
            *(float4*)&sv2[row * 64 + d4 * 4] =
                *(const float4*)&g_v[base + (size_t)(tt0 + row) * 64 + d4 * 4];
        }
        __syncthreads();
#pragma unroll 4
        for (int t = 0; t < 32; t++) {
            float kv = sk2[t * 64 + i];
#pragma unroll
            for (int jj = 0; jj < 16; jj++)
                acc[jj] += kv * sv2[t * 64 + jb + jj];
            if (tid < 64) ks += sk2[t * 64 + tid];
        }
        __syncthreads();
    }

    const size_t ob = (size_t)(bh * NC_ + c) * (D_ * D_);
#pragma unroll
    for (int jj = 0; jj < 16; jj++)
        g_kv[ob + (size_t)i * 64 + jb + jj] = acc[jj];
    if (tid < 64)
        g_ks[(size_t)(bh * NC_ + c) * 64 + tid] = ks;
}

// ---------------------------------------------------------------------------
// Kernel 3: exclusive prefix scan over chunks (in place), 16 blocks
// ---------------------------------------------------------------------------
__global__ void __launch_bounds__(256, 4)
chunk_scan_kernel()
{
    const int tid = threadIdx.x;
    const int bh = blockIdx.x;

    float run[16];
#pragma unroll
    for (int q = 0; q < 16; q++) run[q] = 0.f;

    for (int c = 0; c < NC_; c++) {
        size_t base = (size_t)(bh * NC_ + c) * (D_ * D_);
#pragma unroll
        for (int q = 0; q < 16; q++) {
            size_t e = base + q * 256 + tid;
            float tmp = g_kv[e];
            g_kv[e] = run[q];
            run[q] += tmp;
        }
    }
    if (tid < 64) {
        float kr = 0.f;
        for (int c = 0; c < NC_; c++) {
            size_t e = (size_t)(bh * NC_ + c) * 64 + tid;
            float tmp = g_ks[e];
            g_ks[e] = kr;
            kr += tmp;
        }
    }
}

// ---------------------------------------------------------------------------
// Kernel 4: per-chunk attention, 512 threads. Epilogue writes y as bf16 hi/lo.
// ---------------------------------------------------------------------------
#define SQ_OFF   0
#define SK_OFF   8320
#define SV_OFF   16640
#define SA_OFF   24960
#define SS_OFF   41472
#define SKP_OFF  45632
#define SDEN_OFF 45696
#define SMEM4_FLOATS 45824

__global__ void __launch_bounds__(512, 1)
attn_chunk_kernel()
{
    extern __shared__ float sm[];
    const int tid = threadIdx.x;
    const int bh = blockIdx.x >> 4;
    const int c  = blockIdx.x & 15;

    const size_t base = ((size_t)bh * T_ + c * L_) * 64;

    for (int q = 0; q < 16; q++) {
        int f = q * 512 + tid;
        int row = f >> 6, d = f & 63;
        sm[SQ_OFF + row * 65 + d] = g_phiq[base + f];
        sm[SK_OFF + row * 65 + d] = g_phik[base + f];
        sm[SV_OFF + row * 65 + d] = g_v[base + f];
    }
    {
        size_t sb = (size_t)(bh * NC_ + c) * (D_ * D_);
        for (int q = 0; q < 8; q++) {
            int f = q * 512 + tid;
            int row = f >> 6, d = f & 63;
            sm[SS_OFF + row * 65 + d] = g_kv[sb + f];
        }
        if (tid < 64)
            sm[SKP_OFF + tid] = g_ks[(size_t)(bh * NC_ + c) * 64 + tid];
    }
    __syncthreads();

    const int tr = tid >> 4, tc = tid & 15;   // 32 x 16 thread grid

    // Phase A: A = phiq @ phik^T ; per-thread 4x8
    {
        const int m0 = tr * 4, s0 = tc * 8;
        float acc[4][8];
#pragma unroll
        for (int i = 0; i < 4; i++)
#pragma unroll
            for (int j = 0; j < 8; j++) acc[i][j] = 0.f;

        for (int d = 0; d < 64; d++) {
            float a[4], b[8];
#pragma unroll
            for (int i = 0; i < 4; i++) a[i] = sm[SQ_OFF + (m0 + i) * 65 + d];
#pragma unroll
            for (int j = 0; j < 8; j++) b[j] = sm[SK_OFF + (s0 + j) * 65 + d];
#pragma unroll
            for (int i = 0; i < 4; i++)
#pragma unroll
                for (int j = 0; j < 8; j++) acc[i][j] += a[i] * b[j];
        }
#pragma unroll
        for (int i = 0; i < 4; i++) {
            int t = m0 + i;
#pragma unroll
            for (int j = 0; j < 8; j++) {
                int s = s0 + j;
                sm[SA_OFF + t * 129 + s] = (s <= t) ? acc[i][j] : 0.f;
            }
        }
    }
    __syncthreads();

    // Denominator
    if (tid < 128) {
        int t = tid;
        float rs = 0.f;
        for (int s = 0; s < 128; s++) rs += sm[SA_OFF + t * 129 + s];
        for (int d = 0; d < 64; d++)
            rs += sm[SQ_OFF + t * 65 + d] * sm[SKP_OFF + d];
        sm[SDEN_OFF + t] = fmaxf(rs, EPS_);
    }
    __syncthreads();

    // Phase B: num = A@V + phiq@S; per-thread 4x4; write y bf16 hi/lo
    {
        const int m0 = tr * 4, n0 = tc * 4;
        float num[4][4];
#pragma unroll
        for (int i = 0; i < 4; i++)
#pragma unroll
            for (int j = 0; j < 4; j++) num[i][j] = 0.f;

        for (int k = 0; k < 128; k++) {
            float a[4], b[4];
#pragma unroll
            for (int i = 0; i < 4; i++) a[i] = sm[SA_OFF + (m0 + i) * 129 + k];
#pragma unroll
            for (int j = 0; j < 4; j++) b[j] = sm[SV_OFF + k * 65 + n0 + j];
#pragma unroll
            for (int i = 0; i < 4; i++)
#pragma unroll
                for (int j = 0; j < 4; j++) num[i][j] += a[i] * b[j];
        }
        for (int k = 0; k < 64; k++) {
            float a[4], b[4];
#pragma unroll
            for (int i = 0; i < 4; i++) a[i] = sm[SQ_OFF + (m0 + i) * 65 + k];
#pragma unroll
            for (int j = 0; j < 4; j++) b[j] = sm[SS_OFF + k * 65 + n0 + j];
#pragma unroll
            for (int i = 0; i < 4; i++)
#pragma unroll
                for (int j = 0; j < 4; j++) num[i][j] += a[i] * b[j];
        }

        const int bidx = bh >> 3, h = bh & 7;
#pragma unroll
        for (int i = 0; i < 4; i++) {
            int tl = m0 + i;
            int tg = c * L_ + tl;
            float inv = 1.f / sm[SDEN_OFF + tl];
            size_t ybase = ((size_t)bidx * T_ + tg) * C_ + h * 64 + n0;
#pragma unroll
            for (int p = 0; p < 2; p++) {
                float v0 = num[i][p*2]     * inv;
                float v1 = num[i][p*2 + 1] * inv;
                __nv_bfloat16 h0 = __float2bfloat16(v0);
                __nv_bfloat16 h1 = __float2bfloat16(v1);
                __nv_bfloat162 hh; hh.x = h0; hh.y = h1;
                __nv_bfloat162 ll;
                ll.x = __float2bfloat16(v0 - __bfloat162float(h0));
                ll.y = __float2bfloat16(v1 - __bfloat162float(h1));
                *(__nv_bfloat162*)&g_yhi[ybase + p*2] = hh;
                *(__nv_bfloat162*)&g_ylo[ybase + p*2] = ll;
            }
        }
    }
}

// ---------------------------------------------------------------------------
extern "C" void kernel_launch(void* const* d_in, const int* in_sizes, int n_in,
                              void* d_out, int out_size)
{
    const float* x     = (const float*)d_in[0];
    const float* am    = (const float*)d_in[1];
    const float* wqkv  = (const float*)d_in[2];
    const float* bqkv  = (const float*)d_in[3];
    const float* wproj = (const float*)d_in[4];
    const float* bproj = (const float*)d_in[5];
    float* out = (float*)d_out;

    static bool attr_set = false;
    if (!attr_set) {
        cudaFuncSetAttribute(attn_chunk_kernel,
                             cudaFuncAttributeMaxDynamicSharedMemorySize,
                             SMEM4_FLOATS * sizeof(float));
        cudaFuncSetAttribute(wmma_gemm_kernel<0>,
                             cudaFuncAttributeMaxDynamicSharedMemorySize, G_SMEM);
        cudaFuncSetAttribute(wmma_gemm_kernel<1>,
                             cudaFuncAttributeMaxDynamicSharedMemorySize, G_SMEM);
        attr_set = true;
    }

    __nv_bfloat16 *xhi, *xlo, *wqh, *wql, *wph, *wpl, *yhi, *ylo;
    cudaGetSymbolAddress((void**)&xhi, g_xhi);
    cudaGetSymbolAddress((void**)&xlo, g_xlo);
    cudaGetSymbolAddress((void**)&wqh, g_wqh);
    cudaGetSymbolAddress((void**)&wql, g_wql);
    cudaGetSymbolAddress((void**)&wph, g_wph);
    cudaGetSymbolAddress((void**)&wpl, g_wpl);
    cudaGetSymbolAddress((void**)&yhi, g_yhi);
    cudaGetSymbolAddress((void**)&ylo, g_ylo);

    split_kernel<<<(M_*C_/4 + 255)/256, 256>>>(x, xhi, xlo, M_*C_/4);
    split_kernel<<<(C_*3*C_/4 + 255)/256, 256>>>(wqkv, wqh, wql, C_*3*C_/4);
    split_kernel<<<(C_*C_/4 + 255)/256, 256>>>(wproj, wph, wpl, C_*C_/4);

    dim3 g1(M_ / 128, 1536 / 64);
    wmma_gemm_kernel<0><<<g1, 256, G_SMEM>>>(xhi, xlo, wqh, wql, bqkv, am, nullptr);

    chunk_kv_kernel<<<BH_ * NC_, 256>>>();
    chunk_scan_kernel<<<BH_, 256>>>();

    attn_chunk_kernel<<<BH_ * NC_, 512, SMEM4_FLOATS * sizeof(float)>>>();

    dim3 g5(M_ / 128, 512 / 64);
    wmma_gemm_kernel<1><<<g5, 256, G_SMEM>>>(yhi, ylo, wph, wpl, bproj, nullptr, out);
}

// round 5
// speedup vs baseline: 1.1847x; 1.1847x over previous
#include <cuda_runtime.h>
#include <cuda_bf16.h>
#include <mma.h>
#include <cstdint>
#include <math.h>

using namespace nvcuda;

// Problem constants
#define B_   2
#define T_   2048
#define C_   512
#define H_   8
#define D_   64
#define BH_  (B_*H_)
#define L_   128
#define NC_  (T_/L_)
#define M_   (B_*T_)
#define EPS_ 1e-8f

// Scratch (device globals)
__device__ float g_phiq[BH_*T_*D_];
__device__ float g_phik[BH_*T_*D_];
__device__ float g_v   [BH_*T_*D_];
__device__ float g_kv  [BH_*NC_*D_*D_];
__device__ float g_ks  [BH_*NC_*D_];

// bf16 hi/lo split buffers
__device__ __nv_bfloat16 g_xhi[M_*C_],  g_xlo[M_*C_];
__device__ __nv_bfloat16 g_wqh[C_*3*C_], g_wql[C_*3*C_];
__device__ __nv_bfloat16 g_wph[C_*C_],  g_wpl[C_*C_];
__device__ __nv_bfloat16 g_yhi[M_*C_],  g_ylo[M_*C_];

__device__ __forceinline__ float phi_fn(float x) {
    return (x > 0.f) ? (x + 1.f) : __expf(x);
}

#define CP_ASYNC16(dst_u32, src_ptr) \
    asm volatile("cp.async.cg.shared.global [%0], [%1], 16;" \
        :: "r"(dst_u32), "l"(src_ptr))
#define CP_COMMIT() asm volatile("cp.async.commit_group;")
#define CP_WAIT1()  asm volatile("cp.async.wait_group 1;")
#define CP_WAIT0()  asm volatile("cp.async.wait_group 0;")

// ---------------------------------------------------------------------------
// Split fp32 -> bf16 hi/lo
// ---------------------------------------------------------------------------
__global__ void __launch_bounds__(256)
split_kernel(const float* __restrict__ src,
             __nv_bfloat16* __restrict__ hi,
             __nv_bfloat16* __restrict__ lo, int n4)
{
    int i = blockIdx.x * blockDim.x + threadIdx.x;
    if (i >= n4) return;
    float4 v = ((const float4*)src)[i];
    float vv[4] = {v.x, v.y, v.z, v.w};
    __nv_bfloat162 h2[2], l2[2];
#pragma unroll
    for (int p = 0; p < 2; p++) {
        __nv_bfloat16 h0 = __float2bfloat16(vv[p*2]);
        __nv_bfloat16 h1 = __float2bfloat16(vv[p*2+1]);
        h2[p].x = h0; h2[p].y = h1;
        l2[p].x = __float2bfloat16(vv[p*2]   - __bfloat162float(h0));
        l2[p].y = __float2bfloat16(vv[p*2+1] - __bfloat162float(h1));
    }
    ((__nv_bfloat162*)hi)[i*2]   = h2[0];
    ((__nv_bfloat162*)hi)[i*2+1] = h2[1];
    ((__nv_bfloat162*)lo)[i*2]   = l2[0];
    ((__nv_bfloat162*)lo)[i*2+1] = l2[1];
}

// ---------------------------------------------------------------------------
// cp.async double-buffered wmma bf16 GEMM (3-term split).
// CTA tile 128x128, BK=32, 8 warps (4x2), warp tile 32x64 (2x4 frags).
// SMEM per stage: AHI 128x40 bf16 (10240), ALO, BHI 32x136 bf16 (8704), BLO.
// stage=37888, 2 stages=75776. Cs (128x68 f32 = 34816) overlays stage 0.
// ---------------------------------------------------------------------------
#define G_LDA 40
#define G_LDB 136
#define G_LDC 68
#define G_AHI 0
#define G_ALO 10240
#define G_BHI 20480
#define G_BLO 29184
#define G_STAGE 37888
#define G_SMEM  (2*G_STAGE)

template<int MODE>
__global__ void __launch_bounds__(256, 2)
wmma_gemm_kernel(const __nv_bfloat16* __restrict__ Ahi_g,
                 const __nv_bfloat16* __restrict__ Alo_g,
                 const __nv_bfloat16* __restrict__ Bhi_g,
                 const __nv_bfloat16* __restrict__ Blo_g,
                 const float* __restrict__ bias,
                 const float* __restrict__ am,
                 float* __restrict__ outp)
{
    constexpr int NW = (MODE == 0) ? 1536 : 512;
    extern __shared__ char smem[];
    float* Cs = (float*)smem;

    const int tid = threadIdx.x;
    const int wid = tid >> 5;
    const int bm = blockIdx.x * 128, bn = blockIdx.y * 128;
    const int wr = wid >> 1, wc = wid & 1;   // 4x2 warp grid; warp tile 32x64

    const uint32_t smem_u32 = (uint32_t)__cvta_generic_to_shared(smem);

    // load mappings (uint4 = 8 bf16), 2 per thread per buffer
    const int ar[2] = { tid >> 2, (256 + tid) >> 2 };
    const int ac[2] = { (tid & 3) * 8, ((256 + tid) & 3) * 8 };
    const int brr[2] = { tid >> 4, (256 + tid) >> 4 };
    const int bcc[2] = { (tid & 15) * 8, ((256 + tid) & 15) * 8 };

    auto issue_loads = [&](int s, int k0) {
        const uint32_t st = smem_u32 + s * G_STAGE;
#pragma unroll
        for (int q = 0; q < 2; q++) {
            uint32_t adst = st + G_AHI + (uint32_t)(ar[q] * G_LDA + ac[q]) * 2;
            CP_ASYNC16(adst, &Ahi_g[(size_t)(bm + ar[q]) * 512 + k0 + ac[q]]);
            CP_ASYNC16(adst + (G_ALO - G_AHI),
                       &Alo_g[(size_t)(bm + ar[q]) * 512 + k0 + ac[q]]);
            uint32_t bdst = st + G_BHI + (uint32_t)(brr[q] * G_LDB + bcc[q]) * 2;
            CP_ASYNC16(bdst, &Bhi_g[(size_t)(k0 + brr[q]) * NW + bn + bcc[q]]);
            CP_ASYNC16(bdst + (G_BLO - G_BHI),
                       &Blo_g[(size_t)(k0 + brr[q]) * NW + bn + bcc[q]]);
        }
        CP_COMMIT();
    };

    wmma::fragment<wmma::accumulator, 16, 16, 16, float> acc[2][4];
#pragma unroll
    for (int i = 0; i < 2; i++)
#pragma unroll
        for (int j = 0; j < 4; j++) wmma::fill_fragment(acc[i][j], 0.f);

    issue_loads(0, 0);

    for (int kt = 0; kt < 16; kt++) {
        const int cur = kt & 1;
        if (kt < 15) {
            issue_loads(cur ^ 1, (kt + 1) * 32);
            CP_WAIT1();
        } else {
            CP_WAIT0();
        }
        __syncthreads();

        const char* st = smem + cur * G_STAGE;
        const __nv_bfloat16* As_hi = (const __nv_bfloat16*)(st + G_AHI);
        const __nv_bfloat16* As_lo = (const __nv_bfloat16*)(st + G_ALO);
        const __nv_bfloat16* Bs_hi = (const __nv_bfloat16*)(st + G_BHI);
        const __nv_bfloat16* Bs_lo = (const __nv_bfloat16*)(st + G_BLO);

#pragma unroll
        for (int kk = 0; kk < 32; kk += 16) {
            wmma::fragment<wmma::matrix_a, 16, 16, 16, __nv_bfloat16, wmma::row_major> ah[2], al[2];
            wmma::fragment<wmma::matrix_b, 16, 16, 16, __nv_bfloat16, wmma::row_major> bh[4], bl[4];
#pragma unroll
            for (int i = 0; i < 2; i++) {
                wmma::load_matrix_sync(ah[i], &As_hi[(wr * 32 + i * 16) * G_LDA + kk], G_LDA);
                wmma::load_matrix_sync(al[i], &As_lo[(wr * 32 + i * 16) * G_LDA + kk], G_LDA);
            }
#pragma unroll
            for (int j = 0; j < 4; j++) {
                wmma::load_matrix_sync(bh[j], &Bs_hi[kk * G_LDB + wc * 64 + j * 16], G_LDB);
                wmma::load_matrix_sync(bl[j], &Bs_lo[kk * G_LDB + wc * 64 + j * 16], G_LDB);
            }
#pragma unroll
            for (int i = 0; i < 2; i++)
#pragma unroll
                for (int j = 0; j < 4; j++) {
                    wmma::mma_sync(acc[i][j], ah[i], bh[j], acc[i][j]);
                    wmma::mma_sync(acc[i][j], ah[i], bl[j], acc[i][j]);
                    wmma::mma_sync(acc[i][j], al[i], bh[j], acc[i][j]);
                }
        }
        __syncthreads();
    }

    // Epilogue in two 64-column passes (Cs overlays stage 0 smem)
#pragma unroll
    for (int p = 0; p < 2; p++) {
        if (wc == p) {
#pragma unroll
            for (int i = 0; i < 2; i++)
#pragma unroll
                for (int j = 0; j < 4; j++)
                    wmma::store_matrix_sync(&Cs[(wr * 32 + i * 16) * G_LDC + j * 16],
                                            acc[i][j], G_LDC, wmma::mem_row_major);
        }
        __syncthreads();

        const int row = tid >> 1;
        const int c0  = (tid & 1) * 32;
        const int m = bm + row;
        const int n0 = bn + p * 64 + c0;

        if (MODE == 0) {
            const int b = m >> 11, t = m & 2047;
            const float maskd = am[((size_t)b * 2048 + t) * 2048 + t];
            const int sec = n0 >> 9;
            const int h = (n0 & 511) >> 6;
            float* dst = (sec == 0) ? g_phiq : (sec == 1) ? g_phik : g_v;
            const size_t ob = ((size_t)(b * 8 + h) * 2048 + t) * 64 + (n0 & 63);
#pragma unroll
            for (int c4 = 0; c4 < 32; c4 += 4) {
                float4 bi = *(const float4*)&bias[n0 + c4];
                float bb[4] = {bi.x, bi.y, bi.z, bi.w};
                float ov[4];
#pragma unroll
                for (int u = 0; u < 4; u++) {
                    float val = Cs[row * G_LDC + c0 + c4 + u] + bb[u];
                    if (sec == 0)      ov[u] = phi_fn(val);
                    else if (sec == 1) ov[u] = phi_fn(val) * maskd;
                    else               ov[u] = val * maskd;
                }
                float4 o; o.x = ov[0]; o.y = ov[1]; o.z = ov[2]; o.w = ov[3];
                *(float4*)&dst[ob + c4] = o;
            }
        } else {
#pragma unroll
            for (int c4 = 0; c4 < 32; c4 += 4) {
                float4 bi = *(const float4*)&bias[n0 + c4];
                float4 o;
                o.x = Cs[row * G_LDC + c0 + c4 + 0] + bi.x;
                o.y = Cs[row * G_LDC + c0 + c4 + 1] + bi.y;
                o.z = Cs[row * G_LDC + c0 + c4 + 2] + bi.z;
                o.w = Cs[row * G_LDC + c0 + c4 + 3] + bi.w;
                *(float4*)&outp[(size_t)m * 512 + n0 + c4] = o;
            }
        }
        __syncthreads();
    }
}

// ---------------------------------------------------------------------------
// Kernel 2: per-chunk KV outer-product sums (64x64) + K sums (64)
// ---------------------------------------------------------------------------
__global__ void __launch_bounds__(256, 4)
chunk_kv_kernel()
{
    __shared__ float sk2[32 * 64];
    __shared__ float sv2[32 * 64];

    const int tid = threadIdx.x;
    const int bh = blockIdx.x >> 4;
    const int c  = blockIdx.x & 15;

    const int i  = tid >> 2;
    const int jb = (tid & 3) * 16;

    float acc[16];
#pragma unroll
    for (int jj = 0; jj < 16; jj++) acc[jj] = 0.f;
    float ks = 0.f;

    const size_t base = ((size_t)bh * T_ + c * L_) * 64;

    for (int tt0 = 0; tt0 < 128; tt0 += 32) {
#pragma unroll
        for (int q = 0; q < 2; q++) {
            int f = q * 256 + tid;
            int row = f >> 4, d4 = f & 15;
            *(float4*)&sk2[row * 64 + d4 * 4] =
                *(const float4*)&g_phik[base + (size_t)(tt0 + row) * 64 + d4 * 4];
            *(float4*)&sv2[row * 64 + d4 * 4] =
                *(const float4*)&g_v[base + (size_t)(tt0 + row) * 64 + d4 * 4];
        }
        __syncthreads();
#pragma unroll 4
        for (int t = 0; t < 32; t++) {
            float kv = sk2[t * 64 + i];
#pragma unroll
            for (int jj = 0; jj < 16; jj++)
                acc[jj] += kv * sv2[t * 64 + jb + jj];
            if (tid < 64) ks += sk2[t * 64 + tid];
        }
        __syncthreads();
    }

    const size_t ob = (size_t)(bh * NC_ + c) * (D_ * D_);
#pragma unroll
    for (int jj = 0; jj < 16; jj++)
        g_kv[ob + (size_t)i * 64 + jb + jj] = acc[jj];
    if (tid < 64)
        g_ks[(size_t)(bh * NC_ + c) * 64 + tid] = ks;
}

// ---------------------------------------------------------------------------
// Kernel 3: exclusive prefix scan over chunks
// ---------------------------------------------------------------------------
__global__ void __launch_bounds__(256, 4)
chunk_scan_kernel()
{
    const int tid = threadIdx.x;
    const int bh = blockIdx.x;

    float run[16];
#pragma unroll
    for (int q = 0; q < 16; q++) run[q] = 0.f;

    for (int c = 0; c < NC_; c++) {
        size_t base = (size_t)(bh * NC_ + c) * (D_ * D_);
#pragma unroll
        for (int q = 0; q < 16; q++) {
            size_t e = base + q * 256 + tid;
            float tmp = g_kv[e];
            g_kv[e] = run[q];
            run[q] += tmp;
        }
    }
    if (tid < 64) {
        float kr = 0.f;
        for (int c = 0; c < NC_; c++) {
            size_t e = (size_t)(bh * NC_ + c) * 64 + tid;
            float tmp = g_ks[e];
            g_ks[e] = kr;
            kr += tmp;
        }
    }
}

// ---------------------------------------------------------------------------
// Kernel 4: per-chunk attention, 512 threads; y written as bf16 hi/lo
// ---------------------------------------------------------------------------
#define SQ_OFF   0
#define SK_OFF   8320
#define SV_OFF   16640
#define SA_OFF   24960
#define SS_OFF   41472
#define SKP_OFF  45632
#define SDEN_OFF 45696
#define SMEM4_FLOATS 45824

__global__ void __launch_bounds__(512, 1)
attn_chunk_kernel()
{
    extern __shared__ float sm[];
    const int tid = threadIdx.x;
    const int bh = blockIdx.x >> 4;
    const int c  = blockIdx.x & 15;

    const size_t base = ((size_t)bh * T_ + c * L_) * 64;

    for (int q = 0; q < 16; q++) {
        int f = q * 512 + tid;
        int row = f >> 6, d = f & 63;
        sm[SQ_OFF + row * 65 + d] = g_phiq[base + f];
        sm[SK_OFF + row * 65 + d] = g_phik[base + f];
        sm[SV_OFF + row * 65 + d] = g_v[base + f];
    }
    {
        size_t sb = (size_t)(bh * NC_ + c) * (D_ * D_);
        for (int q = 0; q < 8; q++) {
            int f = q * 512 + tid;
            int row = f >> 6, d = f & 63;
            sm[SS_OFF + row * 65 + d] = g_kv[sb + f];
        }
        if (tid < 64)
            sm[SKP_OFF + tid] = g_ks[(size_t)(bh * NC_ + c) * 64 + tid];
    }
    __syncthreads();

    const int tr = tid >> 4, tc = tid & 15;

    {
        const int m0 = tr * 4, s0 = tc * 8;
        float acc[4][8];
#pragma unroll
        for (int i = 0; i < 4; i++)
#pragma unroll
            for (int j = 0; j < 8; j++) acc[i][j] = 0.f;

        for (int d = 0; d < 64; d++) {
            float a[4], b[8];
#pragma unroll
            for (int i = 0; i < 4; i++) a[i] = sm[SQ_OFF + (m0 + i) * 65 + d];
#pragma unroll
            for (int j = 0; j < 8; j++) b[j] = sm[SK_OFF + (s0 + j) * 65 + d];
#pragma unroll
            for (int i = 0; i < 4; i++)
#pragma unroll
                for (int j = 0; j < 8; j++) acc[i][j] += a[i] * b[j];
        }
#pragma unroll
        for (int i = 0; i < 4; i++) {
            int t = m0 + i;
#pragma unroll
            for (int j = 0; j < 8; j++) {
                int s = s0 + j;
                sm[SA_OFF + t * 129 + s] = (s <= t) ? acc[i][j] : 0.f;
            }
        }
    }
    __syncthreads();

    if (tid < 128) {
        int t = tid;
        float rs = 0.f;
        for (int s = 0; s < 128; s++) rs += sm[SA_OFF + t * 129 + s];
        for (int d = 0; d < 64; d++)
            rs += sm[SQ_OFF + t * 65 + d] * sm[SKP_OFF + d];
        sm[SDEN_OFF + t] = fmaxf(rs, EPS_);
    }
    __syncthreads();

    {
        const int m0 = tr * 4, n0 = tc * 4;
        float num[4][4];
#pragma unroll
        for (int i = 0; i < 4; i++)
#pragma unroll
            for (int j = 0; j < 4; j++) num[i][j] = 0.f;

        for (int k = 0; k < 128; k++) {
            float a[4], b[4];
#pragma unroll
            for (int i = 0; i < 4; i++) a[i] = sm[SA_OFF + (m0 + i) * 129 + k];
#pragma unroll
            for (int j = 0; j < 4; j++) b[j] = sm[SV_OFF + k * 65 + n0 + j];
#pragma unroll
            for (int i = 0; i < 4; i++)
#pragma unroll
                for (int j = 0; j < 4; j++) num[i][j] += a[i] * b[j];
        }
        for (int k = 0; k < 64; k++) {
            float a[4], b[4];
#pragma unroll
            for (int i = 0; i < 4; i++) a[i] = sm[SQ_OFF + (m0 + i) * 65 + k];
#pragma unroll
            for (int j = 0; j < 4; j++) b[j] = sm[SS_OFF + k * 65 + n0 + j];
#pragma unroll
            for (int i = 0; i < 4; i++)
#pragma unroll
                for (int j = 0; j < 4; j++) num[i][j] += a[i] * b[j];
        }

        const int bidx = bh >> 3, h = bh & 7;
#pragma unroll
        for (int i = 0; i < 4; i++) {
            int tl = m0 + i;
            int tg = c * L_ + tl;
            float inv = 1.f / sm[SDEN_OFF + tl];
            size_t ybase = ((size_t)bidx * T_ + tg) * C_ + h * 64 + n0;
#pragma unroll
            for (int p = 0; p < 2; p++) {
                float v0 = num[i][p*2]     * inv;
                float v1 = num[i][p*2 + 1] * inv;
                __nv_bfloat16 h0 = __float2bfloat16(v0);
                __nv_bfloat16 h1 = __float2bfloat16(v1);
                __nv_bfloat162 hh; hh.x = h0; hh.y = h1;
                __nv_bfloat162 ll;
                ll.x = __float2bfloat16(v0 - __bfloat162float(h0));
                ll.y = __float2bfloat16(v1 - __bfloat162float(h1));
                *(__nv_bfloat162*)&g_yhi[ybase + p*2] = hh;
                *(__nv_bfloat162*)&g_ylo[ybase + p*2] = ll;
            }
        }
    }
}

// ---------------------------------------------------------------------------
extern "C" void kernel_launch(void* const* d_in, const int* in_sizes, int n_in,
                              void* d_out, int out_size)
{
    const float* x     = (const float*)d_in[0];
    const float* am    = (const float*)d_in[1];
    const float* wqkv  = (const float*)d_in[2];
    const float* bqkv  = (const float*)d_in[3];
    const float* wproj = (const float*)d_in[4];
    const float* bproj = (const float*)d_in[5];
    float* out = (float*)d_out;

    static bool attr_set = false;
    if (!attr_set) {
        cudaFuncSetAttribute(attn_chunk_kernel,
                             cudaFuncAttributeMaxDynamicSharedMemorySize,
                             SMEM4_FLOATS * sizeof(float));
        cudaFuncSetAttribute(wmma_gemm_kernel<0>,
                             cudaFuncAttributeMaxDynamicSharedMemorySize, G_SMEM);
        cudaFuncSetAttribute(wmma_gemm_kernel<1>,
                             cudaFuncAttributeMaxDynamicSharedMemorySize, G_SMEM);
        attr_set = true;
    }

    __nv_bfloat16 *xhi, *xlo, *wqh, *wql, *wph, *wpl, *yhi, *ylo;
    cudaGetSymbolAddress((void**)&xhi, g_xhi);
    cudaGetSymbolAddress((void**)&xlo, g_xlo);
    cudaGetSymbolAddress((void**)&wqh, g_wqh);
    cudaGetSymbolAddress((void**)&wql, g_wql);
    cudaGetSymbolAddress((void**)&wph, g_wph);
    cudaGetSymbolAddress((void**)&wpl, g_wpl);
    cudaGetSymbolAddress((void**)&yhi, g_yhi);
    cudaGetSymbolAddress((void**)&ylo, g_ylo);

    split_kernel<<<(M_*C_/4 + 255)/256, 256>>>(x, xhi, xlo, M_*C_/4);
    split_kernel<<<(C_*3*C_/4 + 255)/256, 256>>>(wqkv, wqh, wql, C_*3*C_/4);
    split_kernel<<<(C_*C_/4 + 255)/256, 256>>>(wproj, wph, wpl, C_*C_/4);

    dim3 g1(M_ / 128, 1536 / 128);
    wmma_gemm_kernel<0><<<g1, 256, G_SMEM>>>(xhi, xlo, wqh, wql, bqkv, am, nullptr);

    chunk_kv_kernel<<<BH_ * NC_, 256>>>();
    chunk_scan_kernel<<<BH_, 256>>>();

    attn_chunk_kernel<<<BH_ * NC_, 512, SMEM4_FLOATS * sizeof(float)>>>();

    dim3 g5(M_ / 128, 512 / 128);
    wmma_gemm_kernel<1><<<g5, 256, G_SMEM>>>(yhi, ylo, wph, wpl, bproj, nullptr, out);
}

// round 6
// speedup vs baseline: 1.1951x; 1.0088x over previous
#include <cuda_runtime.h>
#include <cuda_bf16.h>
#include <mma.h>
#include <cstdint>
#include <math.h>

using namespace nvcuda;

// Problem constants
#define B_   2
#define T_   2048
#define C_   512
#define H_   8
#define D_   64
#define BH_  (B_*H_)
#define L_   128
#define NC_  (T_/L_)
#define M_   (B_*T_)
#define EPS_ 1e-8f

// Scratch (device globals)
__device__ float g_phiq[BH_*T_*D_];
__device__ float g_phik[BH_*T_*D_];
__device__ float g_v   [BH_*T_*D_];
__device__ float g_kv  [BH_*NC_*D_*D_];
__device__ float g_ks  [BH_*NC_*D_];

// bf16 hi/lo split buffers
__device__ __nv_bfloat16 g_xhi[M_*C_],  g_xlo[M_*C_];
__device__ __nv_bfloat16 g_wqh[C_*3*C_], g_wql[C_*3*C_];
__device__ __nv_bfloat16 g_wph[C_*C_],  g_wpl[C_*C_];
__device__ __nv_bfloat16 g_yhi[M_*C_],  g_ylo[M_*C_];

__device__ __forceinline__ float phi_fn(float x) {
    return (x > 0.f) ? (x + 1.f) : __expf(x);
}

#define CP_ASYNC16(dst_u32, src_ptr) \
    asm volatile("cp.async.cg.shared.global [%0], [%1], 16;" \
        :: "r"(dst_u32), "l"(src_ptr))
#define CP_COMMIT() asm volatile("cp.async.commit_group;")
#define CP_WAIT1()  asm volatile("cp.async.wait_group 1;")
#define CP_WAIT0()  asm volatile("cp.async.wait_group 0;")

// ---------------------------------------------------------------------------
// Split fp32 -> bf16 hi/lo
// ---------------------------------------------------------------------------
__global__ void __launch_bounds__(256)
split_kernel(const float* __restrict__ src,
             __nv_bfloat16* __restrict__ hi,
             __nv_bfloat16* __restrict__ lo, int n4)
{
    int i = blockIdx.x * blockDim.x + threadIdx.x;
    if (i >= n4) return;
    float4 v = ((const float4*)src)[i];
    float vv[4] = {v.x, v.y, v.z, v.w};
    __nv_bfloat162 h2[2], l2[2];
#pragma unroll
    for (int p = 0; p < 2; p++) {
        __nv_bfloat16 h0 = __float2bfloat16(vv[p*2]);
        __nv_bfloat16 h1 = __float2bfloat16(vv[p*2+1]);
        h2[p].x = h0; h2[p].y = h1;
        l2[p].x = __float2bfloat16(vv[p*2]   - __bfloat162float(h0));
        l2[p].y = __float2bfloat16(vv[p*2+1] - __bfloat162float(h1));
    }
    ((__nv_bfloat162*)hi)[i*2]   = h2[0];
    ((__nv_bfloat162*)hi)[i*2+1] = h2[1];
    ((__nv_bfloat162*)lo)[i*2]   = l2[0];
    ((__nv_bfloat162*)lo)[i*2+1] = l2[1];
}

// ---------------------------------------------------------------------------
// 3-stage cp.async pipelined wmma bf16 GEMM (3-term split).
// CTA tile 128x128, BK=32, 8 warps (4x2), warp tile 32x64 (2x4 frags).
// SMEM per stage: AHI 128x40 bf16 (10240), ALO, BHI 32x136 bf16 (8704), BLO.
// stage=37888, 3 stages=113664. Cs (128x68 f32 = 34816) overlays stage 0.
// One __syncthreads per K-tile.
// ---------------------------------------------------------------------------
#define G_LDA 40
#define G_LDB 136
#define G_LDC 68
#define G_AHI 0
#define G_ALO 10240
#define G_BHI 20480
#define G_BLO 29184
#define G_STAGE 37888
#define G_SMEM  (3*G_STAGE)
#define G_KT    16

template<int MODE>
__global__ void __launch_bounds__(256, 2)
wmma_gemm_kernel(const __nv_bfloat16* __restrict__ Ahi_g,
                 const __nv_bfloat16* __restrict__ Alo_g,
                 const __nv_bfloat16* __restrict__ Bhi_g,
                 const __nv_bfloat16* __restrict__ Blo_g,
                 const float* __restrict__ bias,
                 const float* __restrict__ am,
                 float* __restrict__ outp)
{
    constexpr int NW = (MODE == 0) ? 1536 : 512;
    extern __shared__ char smem[];
    float* Cs = (float*)smem;

    const int tid = threadIdx.x;
    const int wid = tid >> 5;
    const int bm = blockIdx.x * 128, bn = blockIdx.y * 128;
    const int wr = wid >> 1, wc = wid & 1;   // 4x2 warp grid; warp tile 32x64

    const uint32_t smem_u32 = (uint32_t)__cvta_generic_to_shared(smem);

    // load mappings (uint4 = 8 bf16), 2 per thread per buffer
    const int ar[2] = { tid >> 2, (256 + tid) >> 2 };
    const int ac[2] = { (tid & 3) * 8, ((256 + tid) & 3) * 8 };
    const int brr[2] = { tid >> 4, (256 + tid) >> 4 };
    const int bcc[2] = { (tid & 15) * 8, ((256 + tid) & 15) * 8 };

    auto issue_loads = [&](int s, int k0) {
        const uint32_t st = smem_u32 + s * G_STAGE;
#pragma unroll
        for (int q = 0; q < 2; q++) {
            uint32_t adst = st + G_AHI + (uint32_t)(ar[q] * G_LDA + ac[q]) * 2;
            CP_ASYNC16(adst, &Ahi_g[(size_t)(bm + ar[q]) * 512 + k0 + ac[q]]);
            CP_ASYNC16(adst + (G_ALO - G_AHI),
                       &Alo_g[(size_t)(bm + ar[q]) * 512 + k0 + ac[q]]);
            uint32_t bdst = st + G_BHI + (uint32_t)(brr[q] * G_LDB + bcc[q]) * 2;
            CP_ASYNC16(bdst, &Bhi_g[(size_t)(k0 + brr[q]) * NW + bn + bcc[q]]);
            CP_ASYNC16(bdst + (G_BLO - G_BHI),
                       &Blo_g[(size_t)(k0 + brr[q]) * NW + bn + bcc[q]]);
        }
        CP_COMMIT();
    };

    wmma::fragment<wmma::accumulator, 16, 16, 16, float> acc[2][4];
#pragma unroll
    for (int i = 0; i < 2; i++)
#pragma unroll
        for (int j = 0; j < 4; j++) wmma::fill_fragment(acc[i][j], 0.f);

    issue_loads(0, 0);
    issue_loads(1, 32);

    int cur = 0;
    for (int kt = 0; kt < G_KT; kt++) {
        if (kt == G_KT - 1) { CP_WAIT0(); } else { CP_WAIT1(); }
        __syncthreads();

        const char* st = smem + cur * G_STAGE;
        const __nv_bfloat16* As_hi = (const __nv_bfloat16*)(st + G_AHI);
        const __nv_bfloat16* As_lo = (const __nv_bfloat16*)(st + G_ALO);
        const __nv_bfloat16* Bs_hi = (const __nv_bfloat16*)(st + G_BHI);
        const __nv_bfloat16* Bs_lo = (const __nv_bfloat16*)(st + G_BLO);

#pragma unroll
        for (int kk = 0; kk < 32; kk += 16) {
            wmma::fragment<wmma::matrix_a, 16, 16, 16, __nv_bfloat16, wmma::row_major> ah[2], al[2];
            wmma::fragment<wmma::matrix_b, 16, 16, 16, __nv_bfloat16, wmma::row_major> bh[4], bl[4];
#pragma unroll
            for (int i = 0; i < 2; i++) {
                wmma::load_matrix_sync(ah[i], &As_hi[(wr * 32 + i * 16) * G_LDA + kk], G_LDA);
                wmma::load_matrix_sync(al[i], &As_lo[(wr * 32 + i * 16) * G_LDA + kk], G_LDA);
            }
#pragma unroll
            for (int j = 0; j < 4; j++) {
                wmma::load_matrix_sync(bh[j], &Bs_hi[kk * G_LDB + wc * 64 + j * 16], G_LDB);
                wmma::load_matrix_sync(bl[j], &Bs_lo[kk * G_LDB + wc * 64 + j * 16], G_LDB);
            }
#pragma unroll
            for (int i = 0; i < 2; i++)
#pragma unroll
                for (int j = 0; j < 4; j++) {
                    wmma::mma_sync(acc[i][j], ah[i], bh[j], acc[i][j]);
                    wmma::mma_sync(acc[i][j], ah[i], bl[j], acc[i][j]);
                    wmma::mma_sync(acc[i][j], al[i], bh[j], acc[i][j]);
                }
        }

        if (kt + 2 < G_KT) issue_loads((cur + 2) % 3, (kt + 2) * 32);
        cur = (cur + 1) % 3;
    }
    __syncthreads();   // retire all readers before Cs overlays stage 0

    // Epilogue in two 64-column passes (Cs overlays stage 0 smem)
#pragma unroll
    for (int p = 0; p < 2; p++) {
        if (wc == p) {
#pragma unroll
            for (int i = 0; i < 2; i++)
#pragma unroll
                for (int j = 0; j < 4; j++)
                    wmma::store_matrix_sync(&Cs[(wr * 32 + i * 16) * G_LDC + j * 16],
                                            acc[i][j], G_LDC, wmma::mem_row_major);
        }
        __syncthreads();

        const int row = tid >> 1;
        const int c0  = (tid & 1) * 32;
        const int m = bm + row;
        const int n0 = bn + p * 64 + c0;

        if (MODE == 0) {
            const int b = m >> 11, t = m & 2047;
            const float maskd = am[((size_t)b * 2048 + t) * 2048 + t];
            const int sec = n0 >> 9;
            const int h = (n0 & 511) >> 6;
            float* dst = (sec == 0) ? g_phiq : (sec == 1) ? g_phik : g_v;
            const size_t ob = ((size_t)(b * 8 + h) * 2048 + t) * 64 + (n0 & 63);
#pragma unroll
            for (int c4 = 0; c4 < 32; c4 += 4) {
                float4 bi = *(const float4*)&bias[n0 + c4];
                float bb[4] = {bi.x, bi.y, bi.z, bi.w};
                float ov[4];
#pragma unroll
                for (int u = 0; u < 4; u++) {
                    float val = Cs[row * G_LDC + c0 + c4 + u] + bb[u];
                    if (sec == 0)      ov[u] = phi_fn(val);
                    else if (sec == 1) ov[u] = phi_fn(val) * maskd;
                    else               ov[u] = val * maskd;
                }
                float4 o; o.x = ov[0]; o.y = ov[1]; o.z = ov[2]; o.w = ov[3];
                *(float4*)&dst[ob + c4] = o;
            }
        } else {
#pragma unroll
            for (int c4 = 0; c4 < 32; c4 += 4) {
                float4 bi = *(const float4*)&bias[n0 + c4];
                float4 o;
                o.x = Cs[row * G_LDC + c0 + c4 + 0] + bi.x;
                o.y = Cs[row * G_LDC + c0 + c4 + 1] + bi.y;
                o.z = Cs[row * G_LDC + c0 + c4 + 2] + bi.z;
                o.w = Cs[row * G_LDC + c0 + c4 + 3] + bi.w;
                *(float4*)&outp[(size_t)m * 512 + n0 + c4] = o;
            }
        }
        __syncthreads();
    }
}

// ---------------------------------------------------------------------------
// Kernel 2: per-chunk KV outer-product sums (64x64) + K sums (64)
// ---------------------------------------------------------------------------
__global__ void __launch_bounds__(256, 4)
chunk_kv_kernel()
{
    __shared__ float sk2[32 * 64];
    __shared__ float sv2[32 * 64];

    const int tid = threadIdx.x;
    const int bh = blockIdx.x >> 4;
    const int c  = blockIdx.x & 15;

    const int i  = tid >> 2;
    const int jb = (tid & 3) * 16;

    float acc[16];
#pragma unroll
    for (int jj = 0; jj < 16; jj++) acc[jj] = 0.f;
    float ks = 0.f;

    const size_t base = ((size_t)bh * T_ + c * L_) * 64;

    for (int tt0 = 0; tt0 < 128; tt0 += 32) {
#pragma unroll
        for (int q = 0; q < 2; q++) {
            int f = q * 256 + tid;
            int row = f >> 4, d4 = f & 15;
            *(float4*)&sk2[row * 64 + d4 * 4] =
                *(const float4*)&g_phik[base + (size_t)(tt0 + row) * 64 + d4 * 4];
            *(float4*)&sv2[row * 64 + d4 * 4] =
                *(const float4*)&g_v[base + (size_t)(tt0 + row) * 64 + d4 * 4];
        }
        __syncthreads();
#pragma unroll 4
        for (int t = 0; t < 32; t++) {
            float kv = sk2[t * 64 + i];
#pragma unroll
            for (int jj = 0; jj < 16; jj++)
                acc[jj] += kv * sv2[t * 64 + jb + jj];
            if (tid < 64) ks += sk2[t * 64 + tid];
        }
        __syncthreads();
    }

    const size_t ob = (size_t)(bh * NC_ + c) * (D_ * D_);
#pragma unroll
    for (int jj = 0; jj < 16; jj++)
        g_kv[ob + (size_t)i * 64 + jb + jj] = acc[jj];
    if (tid < 64)
        g_ks[(size_t)(bh * NC_ + c) * 64 + tid] = ks;
}

// ---------------------------------------------------------------------------
// Kernel 3: exclusive prefix scan over chunks
// ---------------------------------------------------------------------------
__global__ void __launch_bounds__(256, 4)
chunk_scan_kernel()
{
    const int tid = threadIdx.x;
    const int bh = blockIdx.x;

    float run[16];
#pragma unroll
    for (int q = 0; q < 16; q++) run[q] = 0.f;

    for (int c = 0; c < NC_; c++) {
        size_t base = (size_t)(bh * NC_ + c) * (D_ * D_);
#pragma unroll
        for (int q = 0; q < 16; q++) {
            size_t e = base + q * 256 + tid;
            float tmp = g_kv[e];
            g_kv[e] = run[q];
            run[q] += tmp;
        }
    }
    if (tid < 64) {
        float kr = 0.f;
        for (int c = 0; c < NC_; c++) {
            size_t e = (size_t)(bh * NC_ + c) * 64 + tid;
            float tmp = g_ks[e];
            g_ks[e] = kr;
            kr += tmp;
        }
    }
}

// ---------------------------------------------------------------------------
// Kernel 4: per-chunk attention, 512 threads; y written as bf16 hi/lo
// ---------------------------------------------------------------------------
#define SQ_OFF   0
#define SK_OFF   8320
#define SV_OFF   16640
#define SA_OFF   24960
#define SS_OFF   41472
#define SKP_OFF  45632
#define SDEN_OFF 45696
#define SMEM4_FLOATS 45824

__global__ void __launch_bounds__(512, 1)
attn_chunk_kernel()
{
    extern __shared__ float sm[];
    const int tid = threadIdx.x;
    const int bh = blockIdx.x >> 4;
    const int c  = blockIdx.x & 15;

    const size_t base = ((size_t)bh * T_ + c * L_) * 64;

    for (int q = 0; q < 16; q++) {
        int f = q * 512 + tid;
        int row = f >> 6, d = f & 63;
        sm[SQ_OFF + row * 65 + d] = g_phiq[base + f];
        sm[SK_OFF + row * 65 + d] = g_phik[base + f];
        sm[SV_OFF + row * 65 + d] = g_v[base + f];
    }
    {
        size_t sb = (size_t)(bh * NC_ + c) * (D_ * D_);
        for (int q = 0; q < 8; q++) {
            int f = q * 512 + tid;
            int row = f >> 6, d = f & 63;
            sm[SS_OFF + row * 65 + d] = g_kv[sb + f];
        }
        if (tid < 64)
            sm[SKP_OFF + tid] = g_ks[(size_t)(bh * NC_ + c) * 64 + tid];
    }
    __syncthreads();

    const int tr = tid >> 4, tc = tid & 15;

    {
        const int m0 = tr * 4, s0 = tc * 8;
        float acc[4][8];
#pragma unroll
        for (int i = 0; i < 4; i++)
#pragma unroll
            for (int j = 0; j < 8; j++) acc[i][j] = 0.f;

        for (int d = 0; d < 64; d++) {
            float a[4], b[8];
#pragma unroll
            for (int i = 0; i < 4; i++) a[i] = sm[SQ_OFF + (m0 + i) * 65 + d];
#pragma unroll
            for (int j = 0; j < 8; j++) b[j] = sm[SK_OFF + (s0 + j) * 65 + d];
#pragma unroll
            for (int i = 0; i < 4; i++)
#pragma unroll
                for (int j = 0; j < 8; j++) acc[i][j] += a[i] * b[j];
        }
#pragma unroll
        for (int i = 0; i < 4; i++) {
            int t = m0 + i;
#pragma unroll
            for (int j = 0; j < 8; j++) {
                int s = s0 + j;
                sm[SA_OFF + t * 129 + s] = (s <= t) ? acc[i][j] : 0.f;
            }
        }
    }
    __syncthreads();

    if (tid < 128) {
        int t = tid;
        float rs = 0.f;
        for (int s = 0; s < 128; s++) rs += sm[SA_OFF + t * 129 + s];
        for (int d = 0; d < 64; d++)
            rs += sm[SQ_OFF + t * 65 + d] * sm[SKP_OFF + d];
        sm[SDEN_OFF + t] = fmaxf(rs, EPS_);
    }
    __syncthreads();

    {
        const int m0 = tr * 4, n0 = tc * 4;
        float num[4][4];
#pragma unroll
        for (int i = 0; i < 4; i++)
#pragma unroll
            for (int j = 0; j < 4; j++) num[i][j] = 0.f;

        for (int k = 0; k < 128; k++) {
            float a[4], b[4];
#pragma unroll
            for (int i = 0; i < 4; i++) a[i] = sm[SA_OFF + (m0 + i) * 129 + k];
#pragma unroll
            for (int j = 0; j < 4; j++) b[j] = sm[SV_OFF + k * 65 + n0 + j];
#pragma unroll
            for (int i = 0; i < 4; i++)
#pragma unroll
                for (int j = 0; j < 4; j++) num[i][j] += a[i] * b[j];
        }
        for (int k = 0; k < 64; k++) {
            float a[4], b[4];
#pragma unroll
            for (int i = 0; i < 4; i++) a[i] = sm[SQ_OFF + (m0 + i) * 65 + k];
#pragma unroll
            for (int j = 0; j < 4; j++) b[j] = sm[SS_OFF + k * 65 + n0 + j];
#pragma unroll
            for (int i = 0; i < 4; i++)
#pragma unroll
                for (int j = 0; j < 4; j++) num[i][j] += a[i] * b[j];
        }

        const int bidx = bh >> 3, h = bh & 7;
#pragma unroll
        for (int i = 0; i < 4; i++) {
            int tl = m0 + i;
            int tg = c * L_ + tl;
            float inv = 1.f / sm[SDEN_OFF + tl];
            size_t ybase = ((size_t)bidx * T_ + tg) * C_ + h * 64 + n0;
#pragma unroll
            for (int p = 0; p < 2; p++) {
                float v0 = num[i][p*2]     * inv;
                float v1 = num[i][p*2 + 1] * inv;
                __nv_bfloat16 h0 = __float2bfloat16(v0);
                __nv_bfloat16 h1 = __float2bfloat16(v1);
                __nv_bfloat162 hh; hh.x = h0; hh.y = h1;
                __nv_bfloat162 ll;
                ll.x = __float2bfloat16(v0 - __bfloat162float(h0));
                ll.y = __float2bfloat16(v1 - __bfloat162float(h1));
                *(__nv_bfloat162*)&g_yhi[ybase + p*2] = hh;
                *(__nv_bfloat162*)&g_ylo[ybase + p*2] = ll;
            }
        }
    }
}

// ---------------------------------------------------------------------------
extern "C" void kernel_launch(void* const* d_in, const int* in_sizes, int n_in,
                              void* d_out, int out_size)
{
    const float* x     = (const float*)d_in[0];
    const float* am    = (const float*)d_in[1];
    const float* wqkv  = (const float*)d_in[2];
    const float* bqkv  = (const float*)d_in[3];
    const float* wproj = (const float*)d_in[4];
    const float* bproj = (const float*)d_in[5];
    float* out = (float*)d_out;

    static bool attr_set = false;
    if (!attr_set) {
        cudaFuncSetAttribute(attn_chunk_kernel,
                             cudaFuncAttributeMaxDynamicSharedMemorySize,
                             SMEM4_FLOATS * sizeof(float));
        cudaFuncSetAttribute(wmma_gemm_kernel<0>,
                             cudaFuncAttributeMaxDynamicSharedMemorySize, G_SMEM);
        cudaFuncSetAttribute(wmma_gemm_kernel<1>,
                             cudaFuncAttributeMaxDynamicSharedMemorySize, G_SMEM);
        attr_set = true;
    }

    __nv_bfloat16 *xhi, *xlo, *wqh, *wql, *wph, *wpl, *yhi, *ylo;
    cudaGetSymbolAddress((void**)&xhi, g_xhi);
    cudaGetSymbolAddress((void**)&xlo, g_xlo);
    cudaGetSymbolAddress((void**)&wqh, g_wqh);
    cudaGetSymbolAddress((void**)&wql, g_wql);
    cudaGetSymbolAddress((void**)&wph, g_wph);
    cudaGetSymbolAddress((void**)&wpl, g_wpl);
    cudaGetSymbolAddress((void**)&yhi, g_yhi);
    cudaGetSymbolAddress((void**)&ylo, g_ylo);

    split_kernel<<<(M_*C_/4 + 255)/256, 256>>>(x, xhi, xlo, M_*C_/4);
    split_kernel<<<(C_*3*C_/4 + 255)/256, 256>>>(wqkv, wqh, wql, C_*3*C_/4);
    split_kernel<<<(C_*C_/4 + 255)/256, 256>>>(wproj, wph, wpl, C_*C_/4);

    dim3 g1(M_ / 128, 1536 / 128);
    wmma_gemm_kernel<0><<<g1, 256, G_SMEM>>>(xhi, xlo, wqh, wql, bqkv, am, nullptr);

    chunk_kv_kernel<<<BH_ * NC_, 256>>>();
    chunk_scan_kernel<<<BH_, 256>>>();

    attn_chunk_kernel<<<BH_ * NC_, 512, SMEM4_FLOATS * sizeof(float)>>>();

    dim3 g5(M_ / 128, 512 / 128);
    wmma_gemm_kernel<1><<<g5, 256, G_SMEM>>>(yhi, ylo, wph, wpl, bproj, nullptr, out);
}